// round 13
// baseline (speedup 1.0000x reference)
#include <cuda_runtime.h>
#include <cuda_fp16.h>
#include <cstdint>
#include <cstddef>
#include <cstring>

// Problem constants (fixed by the dataset)
constexpr int Gn = 16;
constexpr int Bn = 8192;
constexpr int Kn = 1024;
constexpr int Dn = 64;

constexpr int DP  = 80;              // augmented dim: 64 data + 4 norm + 12 pad
constexpr int RB  = DP * 2;          // 160 bytes per augmented row
constexpr int TM  = 128;             // x rows per CTA (resident)
constexpr int TN  = 128;             // centroids per tile (streamed)
constexpr int NCT = Kn / TN;         // 8 c tiles per CTA
constexpr int NT  = 512;             // threads per CTA

// Augmented f16 centroids (device global scratch; x is converted in-kernel).
//  c row: [ c (64)] [1, 1, c2_hi, c2_lo] [0 x 12]
__device__ __align__(16) uint32_t g_cb[(size_t)Gn * Kn * (RB / 4)];

// Dynamic smem (bytes).
//  x resident: 16KB main (128B rows, XOR swizzle) + 4KB aug (32B rows).
//  c: per warp-group (4 groups) private 32-row slice, triple-buffered.
//     slice buffer = 32*128 main + 32*32 aug = 5120 B.
constexpr int XS0 = 0;
constexpr int CSL = 20480;           // c slice region base
constexpr int SLB = 5120;            // slice buffer size
constexpr int SMEM_TOTAL = 20480 + 12 * SLB;   // 81920 B

__device__ __forceinline__ uint32_t smem_u32(const void* p) {
    uint32_t a;
    asm("{ .reg .u64 t; cvta.to.shared.u64 t, %1; cvt.u32.u64 %0, t; }"
        : "=r"(a) : "l"(p));
    return a;
}
__device__ __forceinline__ float fsqrt_approx(float v) {
    float r;
    asm("sqrt.approx.f32 %0, %1;" : "=f"(r) : "f"(v));
    return r;
}
__device__ __forceinline__ uint32_t pack_f16(float lo, float hi) {
    __half2 h = __floats2half2_rn(lo, hi);   // .x = lo (low half)
    uint32_t u;
    memcpy(&u, &h, 4);
    return u;
}
__device__ __forceinline__ void cp16(uint32_t dst, const void* src) {
    asm volatile("cp.async.cg.shared.global [%0], [%1], 16;"
                 :: "r"(dst), "l"(src) : "memory");
}
#define CP_COMMIT() asm volatile("cp.async.commit_group;" ::: "memory")
#define CP_WAIT0()  asm volatile("cp.async.wait_group 0;" ::: "memory")
#define CP_WAIT1()  asm volatile("cp.async.wait_group 1;" ::: "memory")
#define GBAR(id)    asm volatile("bar.sync %0, 128;" :: "r"(id) : "memory")

__device__ __forceinline__ void ldsm_x4(uint32_t r[4], uint32_t addr) {
    asm volatile("ldmatrix.sync.aligned.m8n8.x4.shared.b16 {%0,%1,%2,%3}, [%4];"
                 : "=r"(r[0]), "=r"(r[1]), "=r"(r[2]), "=r"(r[3]) : "r"(addr));
}
// f16 x f16 -> f16 accumulate: D/C in 2 regs (f16x2 each)
__device__ __forceinline__ void mma_f16(uint32_t c[2], const uint32_t a[4],
                                        uint32_t b0, uint32_t b1) {
    asm volatile(
        "mma.sync.aligned.m16n8k16.row.col.f16.f16.f16.f16 "
        "{%0,%1}, {%2,%3,%4,%5}, {%6,%7}, {%0,%1};"
        : "+r"(c[0]), "+r"(c[1])
        : "r"(a[0]), "r"(a[1]), "r"(a[2]), "r"(a[3]), "r"(b0), "r"(b1));
}
__device__ __forceinline__ void stg_cs2(float* p, float a, float b) {
    asm volatile("st.global.cs.v2.f32 [%0], {%1, %2};"
                 :: "l"(p), "f"(a), "f"(b) : "memory");
}
__device__ __forceinline__ void sts128(uint32_t a, uint4 v) {
    asm volatile("st.shared.v4.b32 [%0], {%1,%2,%3,%4};"
                 :: "r"(a), "r"(v.x), "r"(v.y), "r"(v.z), "r"(v.w) : "memory");
}
// aug address within a slice: 32B rows; 16B chunk q of row r at (2r+q)^((r>>2)&7)
__device__ __forceinline__ uint32_t t1addr(uint32_t base, int row, int q) {
    return base + (uint32_t)((((row * 2 + q) ^ ((row >> 2) & 7)) << 4));
}

// ---------------------------------------------------------------------------
// Pass 1 (tiny): augmented f16 centroid rows (exact fp32 norms, hi/lo split).
// ---------------------------------------------------------------------------
__global__ __launch_bounds__(256)
void prep_c_kernel(const float* __restrict__ cen)
{
    const int t = blockIdx.x * blockDim.x + threadIdx.x;
    if (t >= Gn * Kn) return;
    const float4* src = (const float4*)(cen + (size_t)t * Dn);
    uint4* dst = (uint4*)(g_cb + (size_t)t * (RB / 4));

    float s = 0.f;
#pragma unroll
    for (int i = 0; i < 8; i++) {
        float4 v0 = src[2 * i];
        float4 v1 = src[2 * i + 1];
        s = fmaf(v0.x, v0.x, s); s = fmaf(v0.y, v0.y, s);
        s = fmaf(v0.z, v0.z, s); s = fmaf(v0.w, v0.w, s);
        s = fmaf(v1.x, v1.x, s); s = fmaf(v1.y, v1.y, s);
        s = fmaf(v1.z, v1.z, s); s = fmaf(v1.w, v1.w, s);
        uint4 o;
        o.x = pack_f16(v0.x, v0.y); o.y = pack_f16(v0.z, v0.w);
        o.z = pack_f16(v1.x, v1.y); o.w = pack_f16(v1.z, v1.w);
        dst[i] = o;
    }
    const float hf  = __half2float(__float2half_rn(s));
    const float res = s - hf;
    uint4 aug;
    aug.x = pack_f16(1.f, 1.f); aug.y = pack_f16(hf, res);
    aug.z = 0u; aug.w = 0u;
    dst[8] = aug;
    dst[9] = make_uint4(0u, 0u, 0u, 0u);
}

// Group slice loader: 32 rows x 160B = 320 16B chunks over 128 group threads.
// gsrc points at the slice's first row in g_cb.
__device__ __forceinline__ void load_slice(uint32_t base, const char* gsrc, int gtid)
{
#pragma unroll
    for (int i = 0; i < 3; i++) {
        const int idx = i * 128 + gtid;
        if (idx < 320) {
            const int row = idx / 10;
            const int q   = idx - row * 10;
            const char* src = gsrc + row * RB + q * 16;
            if (q < 8) cp16(base + row * 128 + ((q ^ (row & 7)) << 4), src);
            else       cp16(t1addr(base + 4096, row, q - 8), src);
        }
    }
}

// ---------------------------------------------------------------------------
// Pass 2: x tile resident (converted in-kernel); 4 decoupled warp-groups each
// stream their own 32-row c slice (triple-buffered, named-barrier sync).
// ---------------------------------------------------------------------------
__global__ __launch_bounds__(NT, 2)
void dist_kernel(const float* __restrict__ x, float* __restrict__ out)
{
    extern __shared__ __align__(128) char smem[];
    const uint32_t sb = smem_u32(smem);

    const int tid  = threadIdx.x;
    const int wid  = tid >> 5;
    const int lane = tid & 31;
    const int qid  = lane >> 2;     // 0..7
    const int t4   = lane & 3;      // 0..3

    // Warp-group: warps sharing the same c columns (wid & 3).
    const int gq   = wid & 3;                       // group id 0..3
    const int gtid = ((wid >> 2) << 5) + lane;      // thread id within group
    const int wn   = gq * 32;                       // group n-base in tile
    const int wm   = (wid >> 2) * 32;               // warp m-base: 0/32/64/96

    const int g  = blockIdx.y;
    const int b0 = blockIdx.x * TM;

    // Group's slice rows within g_cb: tile ct covers rows ct*128; group takes
    // +gq*32 .. +gq*32+31.
    const char* cgb = (const char*)g_cb + (size_t)(g * Kn + wn) * RB;

    // Group's 3 slice buffers.
    const uint32_t gbase = sb + CSL + (uint32_t)(gq * 3) * SLB;
    uint32_t ccur = gbase;
    uint32_t cnxt = gbase + SLB;
    uint32_t cpf  = gbase + 2 * SLB;

    // ---- Prologue: issue slices for ct=0, ct=1 (overlaps x conversion). ----
    load_slice(ccur, cgb, gtid);
    CP_COMMIT();
    load_slice(cnxt, cgb + (size_t)TN * RB, gtid);
    CP_COMMIT();

    // ---- Convert resident x tile: fp32 -> f16 aug, exact fp32 norms. ----
    {
        const int row  = tid >> 2;
        const int part = tid & 3;
        const float4* xr = (const float4*)(x + (size_t)(g * Bn + b0 + row) * Dn)
                           + part * 4;
        float4 v0 = xr[0], v1 = xr[1], v2 = xr[2], v3 = xr[3];
        float s = 0.f;
        s = fmaf(v0.x, v0.x, s); s = fmaf(v0.y, v0.y, s);
        s = fmaf(v0.z, v0.z, s); s = fmaf(v0.w, v0.w, s);
        s = fmaf(v1.x, v1.x, s); s = fmaf(v1.y, v1.y, s);
        s = fmaf(v1.z, v1.z, s); s = fmaf(v1.w, v1.w, s);
        s = fmaf(v2.x, v2.x, s); s = fmaf(v2.y, v2.y, s);
        s = fmaf(v2.z, v2.z, s); s = fmaf(v2.w, v2.w, s);
        s = fmaf(v3.x, v3.x, s); s = fmaf(v3.y, v3.y, s);
        s = fmaf(v3.z, v3.z, s); s = fmaf(v3.w, v3.w, s);
        s += __shfl_xor_sync(0xffffffffu, s, 1);
        s += __shfl_xor_sync(0xffffffffu, s, 2);   // full row norm in all 4 lanes

        uint4 m0, m1;
        m0.x = pack_f16(-2.f * v0.x, -2.f * v0.y);
        m0.y = pack_f16(-2.f * v0.z, -2.f * v0.w);
        m0.z = pack_f16(-2.f * v1.x, -2.f * v1.y);
        m0.w = pack_f16(-2.f * v1.z, -2.f * v1.w);
        m1.x = pack_f16(-2.f * v2.x, -2.f * v2.y);
        m1.y = pack_f16(-2.f * v2.z, -2.f * v2.w);
        m1.z = pack_f16(-2.f * v3.x, -2.f * v3.y);
        m1.w = pack_f16(-2.f * v3.z, -2.f * v3.w);
        const int q0 = 2 * part, q1 = 2 * part + 1;
        sts128(sb + XS0 + row * 128 + ((q0 ^ (row & 7)) << 4), m0);
        sts128(sb + XS0 + row * 128 + ((q1 ^ (row & 7)) << 4), m1);

        if (part == 0) {
            const float hf  = __half2float(__float2half_rn(s));
            const float res = s - hf;
            uint4 aug;
            aug.x = pack_f16(hf, res); aug.y = pack_f16(1.f, 1.f);
            aug.z = 0u; aug.w = 0u;
            sts128(t1addr(sb + XS0 + 16384, row, 0), aug);
        } else if (part == 1) {
            sts128(t1addr(sb + XS0 + 16384, row, 1), make_uint4(0u, 0u, 0u, 0u));
        }
    }
    __syncthreads();   // x tile visible to all warps; groups decouple from here

    // Per-lane ldmatrix geometry.
    const int swz    = lane & 7;
    const int a_row  = lane & 15;                        // + wm + mt*16
    const int a_qoff = lane >> 4;                        // 0/1
    const int b_nrow = ((lane >> 4) << 3) + (lane & 7);  // slice-local (+16)
    const int b_qoff = (lane >> 3) & 1;                  // 0/1

    const uint32_t xs0 = sb + XS0;
    const uint32_t xs1 = sb + XS0 + 16384;
    const int bar_id = gq + 1;   // named barriers 1..4

#pragma unroll 1
    for (int ct = 0; ct < NCT; ct++) {
        if (ct == NCT - 1) { CP_WAIT0(); } else { CP_WAIT1(); }
        GBAR(bar_id);      // group's slice loads visible group-wide

        if (ct + 2 < NCT) {
            load_slice(cpf, cgb + (size_t)(ct + 2) * TN * RB, gtid);
            CP_COMMIT();
        }

        const uint32_t cs0 = ccur;
        const uint32_t cs1 = ccur + 4096;

        // acc[mt][nt][h]: f16x2 pair; rows wm+16mt+8h+qid, cols wn+8nt+2t4.
        uint32_t acc[2][4][2];
#pragma unroll
        for (int mt = 0; mt < 2; mt++)
#pragma unroll
            for (int nt = 0; nt < 4; nt++) { acc[mt][nt][0] = 0u; acc[mt][nt][1] = 0u; }

        // ---- k-steps 0..3: main 64 dims. ----
#pragma unroll
        for (int ks = 0; ks < 4; ks++) {
            const uint32_t qa = (uint32_t)(((2 * ks + a_qoff) ^ swz) << 4);
            const uint32_t qb = (uint32_t)(((2 * ks + b_qoff) ^ swz) << 4);

            uint32_t bf[4][2];
            {
                uint32_t r[4];
                ldsm_x4(r, cs0 + (uint32_t)(b_nrow * 128) + qb);
                bf[0][0] = r[0]; bf[0][1] = r[1]; bf[1][0] = r[2]; bf[1][1] = r[3];
                ldsm_x4(r, cs0 + (uint32_t)((16 + b_nrow) * 128) + qb);
                bf[2][0] = r[0]; bf[2][1] = r[1]; bf[3][0] = r[2]; bf[3][1] = r[3];
            }
#pragma unroll
            for (int mt = 0; mt < 2; mt++) {
                uint32_t a[4];
                ldsm_x4(a, xs0 + (uint32_t)((wm + mt * 16 + a_row) * 128) + qa);
#pragma unroll
                for (int nt = 0; nt < 4; nt++)
                    mma_f16(acc[mt][nt], a, bf[nt][0], bf[nt][1]);
            }
        }

        // ---- k-step 4: augmented 16 dims. ----
        {
            uint32_t bf[4][2];
            {
                uint32_t r[4];
                ldsm_x4(r, t1addr(cs1, b_nrow, b_qoff));
                bf[0][0] = r[0]; bf[0][1] = r[1]; bf[1][0] = r[2]; bf[1][1] = r[3];
                ldsm_x4(r, t1addr(cs1, 16 + b_nrow, b_qoff));
                bf[2][0] = r[0]; bf[2][1] = r[1]; bf[3][0] = r[2]; bf[3][1] = r[3];
            }
#pragma unroll
            for (int mt = 0; mt < 2; mt++) {
                uint32_t a[4];
                ldsm_x4(a, t1addr(xs1, wm + mt * 16 + a_row, a_qoff));
#pragma unroll
                for (int nt = 0; nt < 4; nt++)
                    mma_f16(acc[mt][nt], a, bf[nt][0], bf[nt][1]);
            }
        }

        // ---- Epilogue: unpack f16 d^2 -> sqrt -> streaming store. ----
        const int k0 = ct * TN;
#pragma unroll
        for (int mt = 0; mt < 2; mt++) {
            const int row0 = b0 + wm + mt * 16 + qid;
            float* opa = out + (size_t)(g * Bn + row0) * Kn + k0 + wn + 2 * t4;
            float* opb = opa + (size_t)8 * Kn;
#pragma unroll
            for (int nt = 0; nt < 4; nt++) {
                __half2 h0, h1;
                memcpy(&h0, &acc[mt][nt][0], 4);
                memcpy(&h1, &acc[mt][nt][1], 4);
                float2 f0 = __half22float2(h0);   // row0:  cols 2t4, 2t4+1
                float2 f1 = __half22float2(h1);   // row0+8
                stg_cs2(opa + nt * 8, fsqrt_approx(f0.x), fsqrt_approx(f0.y));
                stg_cs2(opb + nt * 8, fsqrt_approx(f1.x), fsqrt_approx(f1.y));
            }
        }

        // Rotate this group's slice buffers.
        const uint32_t t = ccur;
        ccur = cnxt; cnxt = cpf; cpf = t;
    }
}

extern "C" void kernel_launch(void* const* d_in, const int* in_sizes, int n_in,
                              void* d_out, int out_size)
{
    const float* x   = (const float*)d_in[0];   // [G, B, D] fp32
    const float* cen = (const float*)d_in[1];   // [G, K, D] fp32
    float* out = (float*)d_out;                 // [G, B, K] fp32

    static bool attr_set = false;
    if (!attr_set) {
        cudaFuncSetAttribute(dist_kernel,
                             cudaFuncAttributeMaxDynamicSharedMemorySize, SMEM_TOTAL);
        attr_set = true;
    }

    prep_c_kernel<<<(Gn * Kn + 255) / 256, 256>>>(cen);

    dim3 grid(Bn / TM, Gn);                     // (64, 16) = 1024 CTAs
    dist_kernel<<<grid, NT, SMEM_TOTAL>>>(x, out);
}

// round 14
// speedup vs baseline: 1.0406x; 1.0406x over previous
#include <cuda_runtime.h>
#include <cuda_bf16.h>
#include <cstdint>
#include <cstddef>
#include <cstring>

// Problem constants (fixed by the dataset)
constexpr int Gn = 16;
constexpr int Bn = 8192;
constexpr int Kn = 1024;
constexpr int Dn = 64;

constexpr int DP  = 80;              // augmented dim: 64 data + 4 norm + 12 pad
constexpr int RB  = DP * 2;          // 160 bytes per augmented row
constexpr int TM  = 128;             // x rows per CTA (resident)
constexpr int TN  = 128;             // centroids per tile (streamed)
constexpr int NCT = Kn / TN;         // 8 c tiles per CTA
constexpr int NT  = 256;             // threads per CTA

// Augmented bf16 centroids (device global scratch; x is converted in-kernel).
//  c row: [ c (64)] [1, 1, c2_hi, c2_lo] [0 x 12]
__device__ __align__(16) uint32_t g_cb[(size_t)Gn * Kn * (RB / 4)];

// Dynamic smem (bytes). Slot = 16KB main (128B rows, XOR swizzle) + 4KB aug
// (32B rows). x resident in slot 0; c triple-buffered in slots 1..3.
constexpr int XS0 = 0;
constexpr int CBB = 20480;           // c buffer stride
constexpr int SMEM_TOTAL = 20480 * 4;   // 81920 B

__device__ __forceinline__ uint32_t smem_u32(const void* p) {
    uint32_t a;
    asm("{ .reg .u64 t; cvta.to.shared.u64 t, %1; cvt.u32.u64 %0, t; }"
        : "=r"(a) : "l"(p));
    return a;
}
__device__ __forceinline__ float fsqrt_approx(float v) {
    float r;
    asm("sqrt.approx.f32 %0, %1;" : "=f"(r) : "f"(v));
    return r;
}
// packs lo into bits[0:16), hi into bits[16:32)
__device__ __forceinline__ uint32_t pack_bf16(float lo, float hi) {
    uint32_t r;
    asm("cvt.rn.bf16x2.f32 %0, %1, %2;" : "=r"(r) : "f"(hi), "f"(lo));
    return r;
}
__device__ __forceinline__ void cp16(uint32_t dst, const void* src) {
    asm volatile("cp.async.cg.shared.global [%0], [%1], 16;"
                 :: "r"(dst), "l"(src) : "memory");
}
#define CP_COMMIT() asm volatile("cp.async.commit_group;" ::: "memory")
#define CP_WAIT0()  asm volatile("cp.async.wait_group 0;" ::: "memory")
#define CP_WAIT1()  asm volatile("cp.async.wait_group 1;" ::: "memory")

__device__ __forceinline__ void ldsm_x4(uint32_t r[4], uint32_t addr) {
    asm volatile("ldmatrix.sync.aligned.m8n8.x4.shared.b16 {%0,%1,%2,%3}, [%4];"
                 : "=r"(r[0]), "=r"(r[1]), "=r"(r[2]), "=r"(r[3]) : "r"(addr));
}
// bf16 x bf16 -> fp32 accumulate (R7 core)
__device__ __forceinline__ void mma_bf16(float c[4], const uint32_t a[4],
                                         uint32_t b0, uint32_t b1) {
    asm volatile(
        "mma.sync.aligned.m16n8k16.row.col.f32.bf16.bf16.f32 "
        "{%0,%1,%2,%3}, {%4,%5,%6,%7}, {%8,%9}, {%0,%1,%2,%3};"
        : "+f"(c[0]), "+f"(c[1]), "+f"(c[2]), "+f"(c[3])
        : "r"(a[0]), "r"(a[1]), "r"(a[2]), "r"(a[3]), "r"(b0), "r"(b1));
}
__device__ __forceinline__ void stg_cs2(float* p, float a, float b) {
    asm volatile("st.global.cs.v2.f32 [%0], {%1, %2};"
                 :: "l"(p), "f"(a), "f"(b) : "memory");
}
__device__ __forceinline__ void sts128(uint32_t a, uint4 v) {
    asm volatile("st.shared.v4.b32 [%0], {%1,%2,%3,%4};"
                 :: "r"(a), "r"(v.x), "r"(v.y), "r"(v.z), "r"(v.w) : "memory");
}
// aug-tile address: 32B rows; 16B chunk q of row r at flat=(2r+q)^((r>>2)&7)
__device__ __forceinline__ uint32_t t1addr(uint32_t base, int row, int q) {
    return base + (uint32_t)((((row * 2 + q) ^ ((row >> 2) & 7)) << 4));
}

// ---------------------------------------------------------------------------
// Pass 1 (tiny): augmented bf16 centroid rows (exact fp32 norms, hi/lo split).
// ---------------------------------------------------------------------------
__global__ __launch_bounds__(256)
void prep_c_kernel(const float* __restrict__ cen)
{
    const int t = blockIdx.x * blockDim.x + threadIdx.x;
    if (t >= Gn * Kn) return;
    const float4* src = (const float4*)(cen + (size_t)t * Dn);
    uint4* dst = (uint4*)(g_cb + (size_t)t * (RB / 4));

    float s = 0.f;
#pragma unroll
    for (int i = 0; i < 8; i++) {
        float4 v0 = src[2 * i];
        float4 v1 = src[2 * i + 1];
        s = fmaf(v0.x, v0.x, s); s = fmaf(v0.y, v0.y, s);
        s = fmaf(v0.z, v0.z, s); s = fmaf(v0.w, v0.w, s);
        s = fmaf(v1.x, v1.x, s); s = fmaf(v1.y, v1.y, s);
        s = fmaf(v1.z, v1.z, s); s = fmaf(v1.w, v1.w, s);
        uint4 o;
        o.x = pack_bf16(v0.x, v0.y); o.y = pack_bf16(v0.z, v0.w);
        o.z = pack_bf16(v1.x, v1.y); o.w = pack_bf16(v1.z, v1.w);
        dst[i] = o;
    }
    const float hf  = __bfloat162float(__float2bfloat16(s));
    const float res = s - hf;
    uint4 aug;
    aug.x = pack_bf16(1.f, 1.f); aug.y = pack_bf16(hf, res);
    aug.z = 0u; aug.w = 0u;
    dst[8] = aug;
    dst[9] = make_uint4(0u, 0u, 0u, 0u);
}

// c tile loader: 1280 16B chunks (128 rows x 160B) over 256 threads (5 each).
__device__ __forceinline__ void load_ctile(uint32_t base, const char* gsrc, int tid)
{
#pragma unroll
    for (int i = 0; i < 5; i++) {
        const int idx = i * NT + tid;
        const int row = idx / 10;
        const int q   = idx - row * 10;
        const char* src = gsrc + row * RB + q * 16;
        if (q < 8) cp16(base + row * 128 + ((q ^ (row & 7)) << 4), src);
        else       cp16(t1addr(base + 16384, row, q - 8), src);
    }
}

// ---------------------------------------------------------------------------
// Pass 2: x tile resident (converted in-kernel), stream 8 c tiles.
// R7 compute core: 256 threads, 2x4 warps of 64x32 tiles, bf16 -> fp32 acc.
// ---------------------------------------------------------------------------
__global__ __launch_bounds__(NT, 2)
void dist_kernel(const float* __restrict__ x, float* __restrict__ out)
{
    extern __shared__ __align__(128) char smem[];
    const uint32_t sb = smem_u32(smem);

    const int tid  = threadIdx.x;
    const int wid  = tid >> 5;
    const int lane = tid & 31;
    const int qid  = lane >> 2;     // 0..7
    const int t4   = lane & 3;      // 0..3

    const int g  = blockIdx.y;
    const int b0 = blockIdx.x * TM;

    const char* cgb = (const char*)g_cb + (size_t)(g * Kn) * RB;

    // ---- Prologue: issue c tiles 0 and 1 first (overlap with conversion). ----
    load_ctile(sb + CBB, cgb, tid);
    CP_COMMIT();
    load_ctile(sb + 2 * CBB, cgb + (size_t)TN * RB, tid);
    CP_COMMIT();

    // ---- Convert resident x tile: fp32 -> bf16 aug, exact fp32 norms. ----
    // 2 threads per row; each reads 32 floats (8 float4), shfl for the norm.
    {
        const int row  = tid >> 1;
        const int part = tid & 1;
        const float4* xr = (const float4*)(x + (size_t)(g * Bn + b0 + row) * Dn)
                           + part * 8;
        float4 v[8];
#pragma unroll
        for (int i = 0; i < 8; i++) v[i] = xr[i];

        float s = 0.f;
#pragma unroll
        for (int i = 0; i < 8; i++) {
            s = fmaf(v[i].x, v[i].x, s); s = fmaf(v[i].y, v[i].y, s);
            s = fmaf(v[i].z, v[i].z, s); s = fmaf(v[i].w, v[i].w, s);
        }
        s += __shfl_xor_sync(0xffffffffu, s, 1);   // full row norm in both lanes

        // main chunks part*4 .. part*4+3 hold -2x (bf16); chunk j = 8 elems.
#pragma unroll
        for (int j = 0; j < 4; j++) {
            uint4 m;
            m.x = pack_bf16(-2.f * v[2*j].x,   -2.f * v[2*j].y);
            m.y = pack_bf16(-2.f * v[2*j].z,   -2.f * v[2*j].w);
            m.z = pack_bf16(-2.f * v[2*j+1].x, -2.f * v[2*j+1].y);
            m.w = pack_bf16(-2.f * v[2*j+1].z, -2.f * v[2*j+1].w);
            const int q = part * 4 + j;
            sts128(sb + XS0 + row * 128 + ((q ^ (row & 7)) << 4), m);
        }

        // aug chunks: [x2_hi, x2_lo, 1, 1, 0...] then zeros
        if (part == 0) {
            const float hf  = __bfloat162float(__float2bfloat16(s));
            const float res = s - hf;
            uint4 aug;
            aug.x = pack_bf16(hf, res); aug.y = pack_bf16(1.f, 1.f);
            aug.z = 0u; aug.w = 0u;
            sts128(t1addr(sb + XS0 + 16384, row, 0), aug);
        } else {
            sts128(t1addr(sb + XS0 + 16384, row, 1), make_uint4(0u, 0u, 0u, 0u));
        }
    }

    const int wm = (wid >> 2) * 64;   // warp m-base: 0 / 64
    const int wn = (wid & 3) * 32;    // warp n-base: 0/32/64/96

    // Per-lane ldmatrix geometry.
    const int swz    = lane & 7;
    const int a_row  = lane & 15;                        // + wm + mt*16
    const int a_qoff = lane >> 4;                        // 0/1
    const int b_nrow = ((lane >> 4) << 3) + (lane & 7);  // + wn (+16)
    const int b_qoff = (lane >> 3) & 1;                  // 0/1

    const uint32_t xs0 = sb + XS0;
    const uint32_t xs1 = sb + XS0 + 16384;

    // Rotating c-buffer bases.
    uint32_t ccur = sb + CBB;
    uint32_t cnxt = sb + 2 * CBB;
    uint32_t cpf  = sb + 3 * CBB;

#pragma unroll 1
    for (int ct = 0; ct < NCT; ct++) {
        if (ct == NCT - 1) { CP_WAIT0(); } else { CP_WAIT1(); }
        __syncthreads();   // also orders the x conversion STS on ct==0

        if (ct + 2 < NCT) {
            load_ctile(cpf, cgb + (size_t)(ct + 2) * TN * RB, tid);
            CP_COMMIT();
        }

        const uint32_t cs0 = ccur;
        const uint32_t cs1 = ccur + 16384;

        // acc[mt][nt][4] fp32 == d^2; rows wm+16mt+qid (+8), cols wn+8nt+2t4.
        float acc[4][4][4];
#pragma unroll
        for (int mt = 0; mt < 4; mt++)
#pragma unroll
            for (int nt = 0; nt < 4; nt++)
#pragma unroll
                for (int r = 0; r < 4; r++) acc[mt][nt][r] = 0.f;

        // ---- k-steps 0..3: main 64 dims. ----
#pragma unroll
        for (int ks = 0; ks < 4; ks++) {
            const uint32_t qa = (uint32_t)(((2 * ks + a_qoff) ^ swz) << 4);
            const uint32_t qb = (uint32_t)(((2 * ks + b_qoff) ^ swz) << 4);

            uint32_t bf[4][2];
            {
                uint32_t r[4];
                ldsm_x4(r, cs0 + (uint32_t)((wn + b_nrow) * 128) + qb);
                bf[0][0] = r[0]; bf[0][1] = r[1]; bf[1][0] = r[2]; bf[1][1] = r[3];
                ldsm_x4(r, cs0 + (uint32_t)((wn + 16 + b_nrow) * 128) + qb);
                bf[2][0] = r[0]; bf[2][1] = r[1]; bf[3][0] = r[2]; bf[3][1] = r[3];
            }
#pragma unroll
            for (int mt = 0; mt < 4; mt++) {
                uint32_t a[4];
                ldsm_x4(a, xs0 + (uint32_t)((wm + mt * 16 + a_row) * 128) + qa);
#pragma unroll
                for (int nt = 0; nt < 4; nt++)
                    mma_bf16(acc[mt][nt], a, bf[nt][0], bf[nt][1]);
            }
        }

        // ---- k-step 4: augmented 16 dims. ----
        {
            uint32_t bf[4][2];
            {
                uint32_t r[4];
                ldsm_x4(r, t1addr(cs1, wn + b_nrow, b_qoff));
                bf[0][0] = r[0]; bf[0][1] = r[1]; bf[1][0] = r[2]; bf[1][1] = r[3];
                ldsm_x4(r, t1addr(cs1, wn + 16 + b_nrow, b_qoff));
                bf[2][0] = r[0]; bf[2][1] = r[1]; bf[3][0] = r[2]; bf[3][1] = r[3];
            }
#pragma unroll
            for (int mt = 0; mt < 4; mt++) {
                uint32_t a[4];
                ldsm_x4(a, t1addr(xs1, wm + mt * 16 + a_row, a_qoff));
#pragma unroll
                for (int nt = 0; nt < 4; nt++)
                    mma_bf16(acc[mt][nt], a, bf[nt][0], bf[nt][1]);
            }
        }

        // ---- Epilogue: acc IS d^2 -> sqrt -> streaming store. ----
        const int k0 = ct * TN;
#pragma unroll
        for (int mt = 0; mt < 4; mt++) {
            const int row0 = b0 + wm + mt * 16 + qid;
            float* opa = out + (size_t)(g * Bn + row0) * Kn + k0 + wn + 2 * t4;
            float* opb = opa + (size_t)8 * Kn;
#pragma unroll
            for (int nt = 0; nt < 4; nt++) {
                stg_cs2(opa + nt * 8, fsqrt_approx(acc[mt][nt][0]),
                                      fsqrt_approx(acc[mt][nt][1]));
                stg_cs2(opb + nt * 8, fsqrt_approx(acc[mt][nt][2]),
                                      fsqrt_approx(acc[mt][nt][3]));
            }
        }

        // Rotate c buffers.
        const uint32_t t = ccur;
        ccur = cnxt; cnxt = cpf; cpf = t;
    }
}

extern "C" void kernel_launch(void* const* d_in, const int* in_sizes, int n_in,
                              void* d_out, int out_size)
{
    const float* x   = (const float*)d_in[0];   // [G, B, D] fp32
    const float* cen = (const float*)d_in[1];   // [G, K, D] fp32
    float* out = (float*)d_out;                 // [G, B, K] fp32

    static bool attr_set = false;
    if (!attr_set) {
        cudaFuncSetAttribute(dist_kernel,
                             cudaFuncAttributeMaxDynamicSharedMemorySize, SMEM_TOTAL);
        attr_set = true;
    }

    prep_c_kernel<<<(Gn * Kn + 255) / 256, 256>>>(cen);

    dim3 grid(Bn / TM, Gn);                     // (64, 16) = 1024 CTAs
    dist_kernel<<<grid, NT, SMEM_TOTAL>>>(x, out);
}

// round 15
// speedup vs baseline: 1.0658x; 1.0242x over previous
#include <cuda_runtime.h>
#include <cuda_fp16.h>
#include <cstdint>
#include <cstddef>
#include <cstring>

// Problem constants (fixed by the dataset)
constexpr int Gn = 16;
constexpr int Bn = 8192;
constexpr int Kn = 1024;
constexpr int Dn = 64;

constexpr int DP  = 80;              // augmented dim: 64 data + 4 norm + 12 pad
constexpr int RB  = DP * 2;          // 160 bytes per augmented row
constexpr int TM  = 128;             // x rows per CTA (resident)
constexpr int TN  = 128;             // centroids per tile (streamed)
constexpr int NCT = Kn / TN;         // 8 c tiles per CTA
constexpr int NT  = 256;             // threads per CTA

// Augmented f16 centroids (device global scratch; x is converted in-kernel).
//  c row: [ c (64)] [1, 1, c2_hi, c2_lo] [0 x 12]
__device__ __align__(16) uint32_t g_cb[(size_t)Gn * Kn * (RB / 4)];

// Dynamic smem (bytes). Slot = 16KB main (128B rows, XOR swizzle) + 4KB aug
// (32B rows). x resident in slot 0; c triple-buffered in slots 1..3.
constexpr int XS0 = 0;
constexpr int CBB = 20480;           // c buffer stride
constexpr int SMEM_TOTAL = 20480 * 4;   // 81920 B

__device__ __forceinline__ uint32_t smem_u32(const void* p) {
    uint32_t a;
    asm("{ .reg .u64 t; cvta.to.shared.u64 t, %1; cvt.u32.u64 %0, t; }"
        : "=r"(a) : "l"(p));
    return a;
}
__device__ __forceinline__ float fsqrt_approx(float v) {
    float r;
    asm("sqrt.approx.f32 %0, %1;" : "=f"(r) : "f"(v));
    return r;
}
__device__ __forceinline__ uint32_t pack_f16(float lo, float hi) {
    __half2 h = __floats2half2_rn(lo, hi);   // .x = lo (low half)
    uint32_t u;
    memcpy(&u, &h, 4);
    return u;
}
__device__ __forceinline__ void cp16(uint32_t dst, const void* src) {
    asm volatile("cp.async.cg.shared.global [%0], [%1], 16;"
                 :: "r"(dst), "l"(src) : "memory");
}
#define CP_COMMIT() asm volatile("cp.async.commit_group;" ::: "memory")
#define CP_WAIT0()  asm volatile("cp.async.wait_group 0;" ::: "memory")
#define CP_WAIT1()  asm volatile("cp.async.wait_group 1;" ::: "memory")

__device__ __forceinline__ void ldsm_x4(uint32_t r[4], uint32_t addr) {
    asm volatile("ldmatrix.sync.aligned.m8n8.x4.shared.b16 {%0,%1,%2,%3}, [%4];"
                 : "=r"(r[0]), "=r"(r[1]), "=r"(r[2]), "=r"(r[3]) : "r"(addr));
}
// f16 x f16 -> f16 accumulate: D/C in 2 regs (f16x2 each)
__device__ __forceinline__ void mma_f16(uint32_t c[2], const uint32_t a[4],
                                        uint32_t b0, uint32_t b1) {
    asm volatile(
        "mma.sync.aligned.m16n8k16.row.col.f16.f16.f16.f16 "
        "{%0,%1}, {%2,%3,%4,%5}, {%6,%7}, {%0,%1};"
        : "+r"(c[0]), "+r"(c[1])
        : "r"(a[0]), "r"(a[1]), "r"(a[2]), "r"(a[3]), "r"(b0), "r"(b1));
}
__device__ __forceinline__ void stg_cs2(float* p, float a, float b) {
    asm volatile("st.global.cs.v2.f32 [%0], {%1, %2};"
                 :: "l"(p), "f"(a), "f"(b) : "memory");
}
__device__ __forceinline__ void sts128(uint32_t a, uint4 v) {
    asm volatile("st.shared.v4.b32 [%0], {%1,%2,%3,%4};"
                 :: "r"(a), "r"(v.x), "r"(v.y), "r"(v.z), "r"(v.w) : "memory");
}
// aug-tile address: 32B rows; 16B chunk q of row r at flat=(2r+q)^((r>>2)&7)
__device__ __forceinline__ uint32_t t1addr(uint32_t base, int row, int q) {
    return base + (uint32_t)((((row * 2 + q) ^ ((row >> 2) & 7)) << 4));
}

// ---------------------------------------------------------------------------
// Pass 1 (tiny): augmented f16 centroid rows (exact fp32 norms, hi/lo split).
// ---------------------------------------------------------------------------
__global__ __launch_bounds__(256)
void prep_c_kernel(const float* __restrict__ cen)
{
    const int t = blockIdx.x * blockDim.x + threadIdx.x;
    if (t >= Gn * Kn) return;
    const float4* src = (const float4*)(cen + (size_t)t * Dn);
    uint4* dst = (uint4*)(g_cb + (size_t)t * (RB / 4));

    float s = 0.f;
#pragma unroll
    for (int i = 0; i < 8; i++) {
        float4 v0 = src[2 * i];
        float4 v1 = src[2 * i + 1];
        s = fmaf(v0.x, v0.x, s); s = fmaf(v0.y, v0.y, s);
        s = fmaf(v0.z, v0.z, s); s = fmaf(v0.w, v0.w, s);
        s = fmaf(v1.x, v1.x, s); s = fmaf(v1.y, v1.y, s);
        s = fmaf(v1.z, v1.z, s); s = fmaf(v1.w, v1.w, s);
        uint4 o;
        o.x = pack_f16(v0.x, v0.y); o.y = pack_f16(v0.z, v0.w);
        o.z = pack_f16(v1.x, v1.y); o.w = pack_f16(v1.z, v1.w);
        dst[i] = o;
    }
    const float hf  = __half2float(__float2half_rn(s));
    const float res = s - hf;
    uint4 aug;
    aug.x = pack_f16(1.f, 1.f); aug.y = pack_f16(hf, res);
    aug.z = 0u; aug.w = 0u;
    dst[8] = aug;
    dst[9] = make_uint4(0u, 0u, 0u, 0u);
}

// c tile loader: 1280 16B chunks (128 rows x 160B) over 256 threads (5 each).
__device__ __forceinline__ void load_ctile(uint32_t base, const char* gsrc, int tid)
{
#pragma unroll
    for (int i = 0; i < 5; i++) {
        const int idx = i * NT + tid;
        const int row = idx / 10;
        const int q   = idx - row * 10;
        const char* src = gsrc + row * RB + q * 16;
        if (q < 8) cp16(base + row * 128 + ((q ^ (row & 7)) << 4), src);
        else       cp16(t1addr(base + 16384, row, q - 8), src);
    }
}

// ---------------------------------------------------------------------------
// Pass 2: x tile resident, A-fragments HOISTED into registers for the whole
// c-tile loop. 256 threads, 2x4 warps of 64x32 tiles, f16 acc == d^2.
// ---------------------------------------------------------------------------
__global__ __launch_bounds__(NT, 2)
void dist_kernel(const float* __restrict__ x, float* __restrict__ out)
{
    extern __shared__ __align__(128) char smem[];
    const uint32_t sb = smem_u32(smem);

    const int tid  = threadIdx.x;
    const int wid  = tid >> 5;
    const int lane = tid & 31;
    const int qid  = lane >> 2;     // 0..7
    const int t4   = lane & 3;      // 0..3

    const int g  = blockIdx.y;
    const int b0 = blockIdx.x * TM;

    const char* cgb = (const char*)g_cb + (size_t)(g * Kn) * RB;

    // ---- Prologue: issue c tiles 0 and 1 first (overlap with conversion). ----
    load_ctile(sb + CBB, cgb, tid);
    CP_COMMIT();
    load_ctile(sb + 2 * CBB, cgb + (size_t)TN * RB, tid);
    CP_COMMIT();

    // ---- Convert resident x tile: fp32 -> f16 aug, exact fp32 norms. ----
    // 2 threads per row; each reads 32 floats (8 float4), shfl for the norm.
    {
        const int row  = tid >> 1;
        const int part = tid & 1;
        const float4* xr = (const float4*)(x + (size_t)(g * Bn + b0 + row) * Dn)
                           + part * 8;
        float4 v[8];
#pragma unroll
        for (int i = 0; i < 8; i++) v[i] = xr[i];

        float s = 0.f;
#pragma unroll
        for (int i = 0; i < 8; i++) {
            s = fmaf(v[i].x, v[i].x, s); s = fmaf(v[i].y, v[i].y, s);
            s = fmaf(v[i].z, v[i].z, s); s = fmaf(v[i].w, v[i].w, s);
        }
        s += __shfl_xor_sync(0xffffffffu, s, 1);   // full row norm in both lanes

        // main chunks part*4 .. part*4+3 hold -2x (f16); chunk j = 8 elems.
#pragma unroll
        for (int j = 0; j < 4; j++) {
            uint4 m;
            m.x = pack_f16(-2.f * v[2*j].x,   -2.f * v[2*j].y);
            m.y = pack_f16(-2.f * v[2*j].z,   -2.f * v[2*j].w);
            m.z = pack_f16(-2.f * v[2*j+1].x, -2.f * v[2*j+1].y);
            m.w = pack_f16(-2.f * v[2*j+1].z, -2.f * v[2*j+1].w);
            const int q = part * 4 + j;
            sts128(sb + XS0 + row * 128 + ((q ^ (row & 7)) << 4), m);
        }

        // aug chunks: [x2_hi, x2_lo, 1, 1, 0...] then zeros
        if (part == 0) {
            const float hf  = __half2float(__float2half_rn(s));
            const float res = s - hf;
            uint4 aug;
            aug.x = pack_f16(hf, res); aug.y = pack_f16(1.f, 1.f);
            aug.z = 0u; aug.w = 0u;
            sts128(t1addr(sb + XS0 + 16384, row, 0), aug);
        } else {
            sts128(t1addr(sb + XS0 + 16384, row, 1), make_uint4(0u, 0u, 0u, 0u));
        }
    }
    __syncthreads();   // x tile visible; A fragments can be loaded

    const int wm = (wid >> 2) * 64;   // warp m-base: 0 / 64
    const int wn = (wid & 3) * 32;    // warp n-base: 0/32/64/96

    // Per-lane ldmatrix geometry.
    const int swz    = lane & 7;
    const int a_row  = lane & 15;                        // + wm + mt*16
    const int a_qoff = lane >> 4;                        // 0/1
    const int b_nrow = ((lane >> 4) << 3) + (lane & 7);  // + wn (+16)
    const int b_qoff = (lane >> 3) & 1;                  // 0/1

    const uint32_t xs0 = sb + XS0;
    const uint32_t xs1 = sb + XS0 + 16384;

    // ---- HOIST: main A fragments for all 4 k-steps x 4 m-tiles (64 regs).
    uint32_t afr[4][4][4];
#pragma unroll
    for (int ks = 0; ks < 4; ks++) {
        const uint32_t qa = (uint32_t)(((2 * ks + a_qoff) ^ swz) << 4);
#pragma unroll
        for (int mt = 0; mt < 4; mt++)
            ldsm_x4(afr[ks][mt], xs0 + (uint32_t)((wm + mt * 16 + a_row) * 128) + qa);
    }

    // Rotating c-buffer bases.
    uint32_t ccur = sb + CBB;
    uint32_t cnxt = sb + 2 * CBB;
    uint32_t cpf  = sb + 3 * CBB;

#pragma unroll 1
    for (int ct = 0; ct < NCT; ct++) {
        if (ct == NCT - 1) { CP_WAIT0(); } else { CP_WAIT1(); }
        __syncthreads();

        if (ct + 2 < NCT) {
            load_ctile(cpf, cgb + (size_t)(ct + 2) * TN * RB, tid);
            CP_COMMIT();
        }

        const uint32_t cs0 = ccur;
        const uint32_t cs1 = ccur + 16384;

        // acc[mt][nt][h]: f16x2 pair; rows wm+16mt+8h+qid, cols wn+8nt+2t4.
        uint32_t acc[4][4][2];
#pragma unroll
        for (int mt = 0; mt < 4; mt++)
#pragma unroll
            for (int nt = 0; nt < 4; nt++) { acc[mt][nt][0] = 0u; acc[mt][nt][1] = 0u; }

        // ---- k-steps 0..3: main 64 dims (A from registers). ----
#pragma unroll
        for (int ks = 0; ks < 4; ks++) {
            const uint32_t qb = (uint32_t)(((2 * ks + b_qoff) ^ swz) << 4);
            uint32_t bf[4][2];
            {
                uint32_t r[4];
                ldsm_x4(r, cs0 + (uint32_t)((wn + b_nrow) * 128) + qb);
                bf[0][0] = r[0]; bf[0][1] = r[1]; bf[1][0] = r[2]; bf[1][1] = r[3];
                ldsm_x4(r, cs0 + (uint32_t)((wn + 16 + b_nrow) * 128) + qb);
                bf[2][0] = r[0]; bf[2][1] = r[1]; bf[3][0] = r[2]; bf[3][1] = r[3];
            }
#pragma unroll
            for (int mt = 0; mt < 4; mt++)
#pragma unroll
                for (int nt = 0; nt < 4; nt++)
                    mma_f16(acc[mt][nt], afr[ks][mt], bf[nt][0], bf[nt][1]);
        }

        // ---- k-step 4: augmented 16 dims (A-aug per tile; 4 LDSM). ----
        {
            uint32_t bf[4][2];
            {
                uint32_t r[4];
                ldsm_x4(r, t1addr(cs1, wn + b_nrow, b_qoff));
                bf[0][0] = r[0]; bf[0][1] = r[1]; bf[1][0] = r[2]; bf[1][1] = r[3];
                ldsm_x4(r, t1addr(cs1, wn + 16 + b_nrow, b_qoff));
                bf[2][0] = r[0]; bf[2][1] = r[1]; bf[3][0] = r[2]; bf[3][1] = r[3];
            }
#pragma unroll
            for (int mt = 0; mt < 4; mt++) {
                uint32_t a[4];
                ldsm_x4(a, t1addr(xs1, wm + mt * 16 + a_row, a_qoff));
#pragma unroll
                for (int nt = 0; nt < 4; nt++)
                    mma_f16(acc[mt][nt], a, bf[nt][0], bf[nt][1]);
            }
        }

        // ---- Epilogue: unpack f16 d^2 -> sqrt -> streaming store. ----
        const int k0 = ct * TN;
#pragma unroll
        for (int mt = 0; mt < 4; mt++) {
            const int row0 = b0 + wm + mt * 16 + qid;
            float* opa = out + (size_t)(g * Bn + row0) * Kn + k0 + wn + 2 * t4;
            float* opb = opa + (size_t)8 * Kn;
#pragma unroll
            for (int nt = 0; nt < 4; nt++) {
                __half2 h0, h1;
                memcpy(&h0, &acc[mt][nt][0], 4);
                memcpy(&h1, &acc[mt][nt][1], 4);
                float2 f0 = __half22float2(h0);   // row0:  cols 2t4, 2t4+1
                float2 f1 = __half22float2(h1);   // row0+8
                stg_cs2(opa + nt * 8, fsqrt_approx(f0.x), fsqrt_approx(f0.y));
                stg_cs2(opb + nt * 8, fsqrt_approx(f1.x), fsqrt_approx(f1.y));
            }
        }

        // Rotate c buffers.
        const uint32_t t = ccur;
        ccur = cnxt; cnxt = cpf; cpf = t;
    }
}

extern "C" void kernel_launch(void* const* d_in, const int* in_sizes, int n_in,
                              void* d_out, int out_size)
{
    const float* x   = (const float*)d_in[0];   // [G, B, D] fp32
    const float* cen = (const float*)d_in[1];   // [G, K, D] fp32
    float* out = (float*)d_out;                 // [G, B, K] fp32

    static bool attr_set = false;
    if (!attr_set) {
        cudaFuncSetAttribute(dist_kernel,
                             cudaFuncAttributeMaxDynamicSharedMemorySize, SMEM_TOTAL);
        attr_set = true;
    }

    prep_c_kernel<<<(Gn * Kn + 255) / 256, 256>>>(cen);

    dim3 grid(Bn / TM, Gn);                     // (64, 16) = 1024 CTAs
    dist_kernel<<<grid, NT, SMEM_TOTAL>>>(x, out);
}

// round 16
// speedup vs baseline: 1.1659x; 1.0939x over previous
#include <cuda_runtime.h>
#include <cuda_fp16.h>
#include <cstdint>
#include <cstddef>
#include <cstring>

// Problem constants (fixed by the dataset)
constexpr int Gn = 16;
constexpr int Bn = 8192;
constexpr int Kn = 1024;
constexpr int Dn = 64;

constexpr int RB  = 128;             // bytes per f16 row (64 dims, no aug)
constexpr int TM  = 128;             // x rows per CTA (resident)
constexpr int TN  = 128;             // centroids per tile (streamed)
constexpr int NCT = Kn / TN;         // 8 c tiles per CTA
constexpr int NT  = 256;             // threads per CTA

// f16 centroids + f16 squared norms (device global scratch).
__device__ __align__(16) uint32_t g_cb[(size_t)Gn * Kn * (RB / 4)];
__device__ __align__(16) unsigned short g_c2h[Gn * Kn];

// Dynamic smem (bytes). Slot = 16KB main (128B rows, XOR swizzle) + 256B norms.
// x resident in slot 0; c triple-buffered in slots 1..3.
constexpr int SLOT = 16640;          // 16384 + 256
constexpr int XS0  = 0;
constexpr int CBB  = SLOT;           // first c buffer
constexpr int SMEM_TOTAL = SLOT * 4; // 66560 B

__device__ __forceinline__ uint32_t smem_u32(const void* p) {
    uint32_t a;
    asm("{ .reg .u64 t; cvta.to.shared.u64 t, %1; cvt.u32.u64 %0, t; }"
        : "=r"(a) : "l"(p));
    return a;
}
__device__ __forceinline__ float fsqrt_approx(float v) {
    float r;
    asm("sqrt.approx.f32 %0, %1;" : "=f"(r) : "f"(v));
    return r;
}
__device__ __forceinline__ uint32_t pack_f16(float lo, float hi) {
    __half2 h = __floats2half2_rn(lo, hi);   // .x = lo (low half)
    uint32_t u;
    memcpy(&u, &h, 4);
    return u;
}
__device__ __forceinline__ uint32_t hadd2u(uint32_t a, uint32_t b) {
    uint32_t r;
    asm("add.rn.f16x2 %0, %1, %2;" : "=r"(r) : "r"(a), "r"(b));
    return r;
}
__device__ __forceinline__ void cp16(uint32_t dst, const void* src) {
    asm volatile("cp.async.cg.shared.global [%0], [%1], 16;"
                 :: "r"(dst), "l"(src) : "memory");
}
#define CP_COMMIT() asm volatile("cp.async.commit_group;" ::: "memory")
#define CP_WAIT0()  asm volatile("cp.async.wait_group 0;" ::: "memory")
#define CP_WAIT1()  asm volatile("cp.async.wait_group 1;" ::: "memory")

__device__ __forceinline__ void ldsm_x4(uint32_t r[4], uint32_t addr) {
    asm volatile("ldmatrix.sync.aligned.m8n8.x4.shared.b16 {%0,%1,%2,%3}, [%4];"
                 : "=r"(r[0]), "=r"(r[1]), "=r"(r[2]), "=r"(r[3]) : "r"(addr));
}
// f16 x f16 -> f16 accumulate: D/C in 2 regs (f16x2 each)
__device__ __forceinline__ void mma_f16(uint32_t c[2], const uint32_t a[4],
                                        uint32_t b0, uint32_t b1) {
    asm volatile(
        "mma.sync.aligned.m16n8k16.row.col.f16.f16.f16.f16 "
        "{%0,%1}, {%2,%3,%4,%5}, {%6,%7}, {%0,%1};"
        : "+r"(c[0]), "+r"(c[1])
        : "r"(a[0]), "r"(a[1]), "r"(a[2]), "r"(a[3]), "r"(b0), "r"(b1));
}
__device__ __forceinline__ void stg_cs2(float* p, float a, float b) {
    asm volatile("st.global.cs.v2.f32 [%0], {%1, %2};"
                 :: "l"(p), "f"(a), "f"(b) : "memory");
}
__device__ __forceinline__ void sts128(uint32_t a, uint4 v) {
    asm volatile("st.shared.v4.b32 [%0], {%1,%2,%3,%4};"
                 :: "r"(a), "r"(v.x), "r"(v.y), "r"(v.z), "r"(v.w) : "memory");
}

// ---------------------------------------------------------------------------
// Pass 1 (tiny): f16 centroid rows + f16 squared norms (fp32-exact reduce).
// ---------------------------------------------------------------------------
__global__ __launch_bounds__(256)
void prep_c_kernel(const float* __restrict__ cen)
{
    const int t = blockIdx.x * blockDim.x + threadIdx.x;
    if (t >= Gn * Kn) return;
    const float4* src = (const float4*)(cen + (size_t)t * Dn);
    uint4* dst = (uint4*)(g_cb + (size_t)t * (RB / 4));

    float s = 0.f;
#pragma unroll
    for (int i = 0; i < 8; i++) {
        float4 v0 = src[2 * i];
        float4 v1 = src[2 * i + 1];
        s = fmaf(v0.x, v0.x, s); s = fmaf(v0.y, v0.y, s);
        s = fmaf(v0.z, v0.z, s); s = fmaf(v0.w, v0.w, s);
        s = fmaf(v1.x, v1.x, s); s = fmaf(v1.y, v1.y, s);
        s = fmaf(v1.z, v1.z, s); s = fmaf(v1.w, v1.w, s);
        uint4 o;
        o.x = pack_f16(v0.x, v0.y); o.y = pack_f16(v0.z, v0.w);
        o.z = pack_f16(v1.x, v1.y); o.w = pack_f16(v1.z, v1.w);
        dst[i] = o;
    }
    __half h = __float2half_rn(s);
    unsigned short hb;
    memcpy(&hb, &h, 2);
    g_c2h[t] = hb;
}

// c tile loader: 1024 main 16B chunks + 16 norm chunks over 256 threads.
__device__ __forceinline__ void load_ctile(uint32_t base, const char* gsrc,
                                           const char* c2src, int tid)
{
#pragma unroll
    for (int i = 0; i < 5; i++) {
        const int idx = i * NT + tid;
        if (idx < 1024) {
            const int row = idx >> 3;
            const int q   = idx & 7;
            cp16(base + row * 128 + ((q ^ (row & 7)) << 4), gsrc + row * RB + q * 16);
        } else if (idx < 1040) {
            const int j = idx - 1024;
            cp16(base + 16384 + j * 16, c2src + j * 16);
        }
    }
}

// ---------------------------------------------------------------------------
// Pass 2: x resident (converted in-kernel), A-fragments hoisted, 8 c tiles
// streamed. Accumulators INITIALIZED to f16(x2+c2): no aug MMA step.
// ---------------------------------------------------------------------------
__global__ __launch_bounds__(NT, 2)
void dist_kernel(const float* __restrict__ x, float* __restrict__ out)
{
    extern __shared__ __align__(128) char smem[];
    const uint32_t sb = smem_u32(smem);

    const int tid  = threadIdx.x;
    const int wid  = tid >> 5;
    const int lane = tid & 31;
    const int qid  = lane >> 2;     // 0..7
    const int t4   = lane & 3;      // 0..3

    const int g  = blockIdx.y;
    const int b0 = blockIdx.x * TM;

    const char* cgb = (const char*)g_cb + (size_t)(g * Kn) * RB;
    const char* c2g = (const char*)g_c2h + (size_t)(g * Kn) * 2;

    // ---- Prologue: issue c tiles 0 and 1 (overlaps the x conversion). ----
    load_ctile(sb + CBB, cgb, c2g, tid);
    CP_COMMIT();
    load_ctile(sb + 2 * CBB, cgb + (size_t)TN * RB, c2g + TN * 2, tid);
    CP_COMMIT();

    // ---- Convert resident x tile: fp32 -> f16 (-2x), f16 norm to smem. ----
    // 2 threads per row; each reads 32 floats (8 float4), shfl for the norm.
    {
        const int row  = tid >> 1;
        const int part = tid & 1;
        const float4* xr = (const float4*)(x + (size_t)(g * Bn + b0 + row) * Dn)
                           + part * 8;
        float4 v[8];
#pragma unroll
        for (int i = 0; i < 8; i++) v[i] = xr[i];

        float s = 0.f;
#pragma unroll
        for (int i = 0; i < 8; i++) {
            s = fmaf(v[i].x, v[i].x, s); s = fmaf(v[i].y, v[i].y, s);
            s = fmaf(v[i].z, v[i].z, s); s = fmaf(v[i].w, v[i].w, s);
        }
        s += __shfl_xor_sync(0xffffffffu, s, 1);   // full row norm in both lanes

        // main chunks part*4 .. part*4+3 hold -2x (f16); chunk j = 8 elems.
#pragma unroll
        for (int j = 0; j < 4; j++) {
            uint4 m;
            m.x = pack_f16(-2.f * v[2*j].x,   -2.f * v[2*j].y);
            m.y = pack_f16(-2.f * v[2*j].z,   -2.f * v[2*j].w);
            m.z = pack_f16(-2.f * v[2*j+1].x, -2.f * v[2*j+1].y);
            m.w = pack_f16(-2.f * v[2*j+1].z, -2.f * v[2*j+1].w);
            const int q = part * 4 + j;
            sts128(sb + XS0 + row * 128 + ((q ^ (row & 7)) << 4), m);
        }

        if (part == 0) {
            __half h = __float2half_rn(s);
            unsigned short hb;
            memcpy(&hb, &h, 2);
            asm volatile("st.shared.u16 [%0], %1;"
                         :: "r"(sb + XS0 + 16384 + (uint32_t)(row * 2)), "h"(hb)
                         : "memory");
        }
    }
    __syncthreads();   // x tile + norms visible

    const int wm = (wid >> 2) * 64;   // warp m-base: 0 / 64
    const int wn = (wid & 3) * 32;    // warp n-base: 0/32/64/96

    // Per-lane ldmatrix geometry.
    const int swz    = lane & 7;
    const int a_row  = lane & 15;                        // + wm + mt*16
    const int a_qoff = lane >> 4;                        // 0/1
    const int b_nrow = ((lane >> 4) << 3) + (lane & 7);  // + wn (+16)
    const int b_qoff = (lane >> 3) & 1;                  // 0/1

    const uint32_t xs0 = sb + XS0;

    // ---- HOIST: main A fragments for all 4 k-steps x 4 m-tiles (64 regs).
    uint32_t afr[4][4][4];
#pragma unroll
    for (int ks = 0; ks < 4; ks++) {
        const uint32_t qa = (uint32_t)(((2 * ks + a_qoff) ^ swz) << 4);
#pragma unroll
        for (int mt = 0; mt < 4; mt++)
            ldsm_x4(afr[ks][mt], xs0 + (uint32_t)((wm + mt * 16 + a_row) * 128) + qa);
    }

    // ---- HOIST: x2 duplicated into half2 per (mt, h) row. ----
    uint32_t x2d[4][2];
#pragma unroll
    for (int mt = 0; mt < 4; mt++)
#pragma unroll
        for (int h = 0; h < 2; h++) {
            const int row = wm + mt * 16 + h * 8 + qid;
            unsigned short hb;
            asm volatile("ld.shared.u16 %0, [%1];"
                         : "=h"(hb) : "r"(xs0 + 16384 + (uint32_t)(row * 2)));
            x2d[mt][h] = (uint32_t)hb | ((uint32_t)hb << 16);
        }

    // Rotating c-buffer bases.
    uint32_t ccur = sb + CBB;
    uint32_t cnxt = sb + 2 * CBB;
    uint32_t cpf  = sb + 3 * CBB;

#pragma unroll 1
    for (int ct = 0; ct < NCT; ct++) {
        if (ct == NCT - 1) { CP_WAIT0(); } else { CP_WAIT1(); }
        __syncthreads();

        if (ct + 2 < NCT) {
            load_ctile(cpf, cgb + (size_t)(ct + 2) * TN * RB,
                       c2g + (ct + 2) * TN * 2, tid);
            CP_COMMIT();
        }

        const uint32_t cs0 = ccur;

        // c2 pairs for this tile: cols wn + nt*8 + {2t4, 2t4+1} (broadcast LDS).
        uint32_t c2p[4];
#pragma unroll
        for (int nt = 0; nt < 4; nt++) {
            asm volatile("ld.shared.b32 %0, [%1];"
                         : "=r"(c2p[nt])
                         : "r"(ccur + 16384 + (uint32_t)((wn + nt * 8 + 2 * t4) * 2)));
        }

        // ---- Init acc = f16x2(x2 + c2): replaces the aug MMA k-step. ----
        uint32_t acc[4][4][2];
#pragma unroll
        for (int mt = 0; mt < 4; mt++)
#pragma unroll
            for (int nt = 0; nt < 4; nt++) {
                acc[mt][nt][0] = hadd2u(x2d[mt][0], c2p[nt]);
                acc[mt][nt][1] = hadd2u(x2d[mt][1], c2p[nt]);
            }

        // ---- k-steps 0..3: main 64 dims (A from registers). ----
#pragma unroll
        for (int ks = 0; ks < 4; ks++) {
            const uint32_t qb = (uint32_t)(((2 * ks + b_qoff) ^ swz) << 4);
            uint32_t bf[4][2];
            {
                uint32_t r[4];
                ldsm_x4(r, cs0 + (uint32_t)((wn + b_nrow) * 128) + qb);
                bf[0][0] = r[0]; bf[0][1] = r[1]; bf[1][0] = r[2]; bf[1][1] = r[3];
                ldsm_x4(r, cs0 + (uint32_t)((wn + 16 + b_nrow) * 128) + qb);
                bf[2][0] = r[0]; bf[2][1] = r[1]; bf[3][0] = r[2]; bf[3][1] = r[3];
            }
#pragma unroll
            for (int mt = 0; mt < 4; mt++)
#pragma unroll
                for (int nt = 0; nt < 4; nt++)
                    mma_f16(acc[mt][nt], afr[ks][mt], bf[nt][0], bf[nt][1]);
        }

        // ---- Epilogue: unpack f16 d^2 -> sqrt -> streaming store. ----
        const int k0 = ct * TN;
#pragma unroll
        for (int mt = 0; mt < 4; mt++) {
            const int row0 = b0 + wm + mt * 16 + qid;
            float* opa = out + (size_t)(g * Bn + row0) * Kn + k0 + wn + 2 * t4;
            float* opb = opa + (size_t)8 * Kn;
#pragma unroll
            for (int nt = 0; nt < 4; nt++) {
                __half2 h0, h1;
                memcpy(&h0, &acc[mt][nt][0], 4);
                memcpy(&h1, &acc[mt][nt][1], 4);
                float2 f0 = __half22float2(h0);   // row0:  cols 2t4, 2t4+1
                float2 f1 = __half22float2(h1);   // row0+8
                stg_cs2(opa + nt * 8, fsqrt_approx(fmaxf(f0.x, 0.f)),
                                      fsqrt_approx(fmaxf(f0.y, 0.f)));
                stg_cs2(opb + nt * 8, fsqrt_approx(fmaxf(f1.x, 0.f)),
                                      fsqrt_approx(fmaxf(f1.y, 0.f)));
            }
        }

        // Rotate c buffers.
        const uint32_t t = ccur;
        ccur = cnxt; cnxt = cpf; cpf = t;
    }
}

extern "C" void kernel_launch(void* const* d_in, const int* in_sizes, int n_in,
                              void* d_out, int out_size)
{
    const float* x   = (const float*)d_in[0];   // [G, B, D] fp32
    const float* cen = (const float*)d_in[1];   // [G, K, D] fp32
    float* out = (float*)d_out;                 // [G, B, K] fp32

    static bool attr_set = false;
    if (!attr_set) {
        cudaFuncSetAttribute(dist_kernel,
                             cudaFuncAttributeMaxDynamicSharedMemorySize, SMEM_TOTAL);
        attr_set = true;
    }

    prep_c_kernel<<<(Gn * Kn + 255) / 256, 256>>>(cen);

    dim3 grid(Bn / TM, Gn);                     // (64, 16) = 1024 CTAs
    dist_kernel<<<grid, NT, SMEM_TOTAL>>>(x, out);
}

// round 17
// speedup vs baseline: 1.1927x; 1.0230x over previous
#include <cuda_runtime.h>
#include <cuda_fp16.h>
#include <cstdint>
#include <cstddef>
#include <cstring>

// Problem constants (fixed by the dataset)
constexpr int Gn = 16;
constexpr int Bn = 8192;
constexpr int Kn = 1024;
constexpr int Dn = 64;

constexpr int RB  = 128;             // bytes per f16 row (64 dims)
constexpr int TM  = 128;             // x rows per CTA (resident)
constexpr int TN  = 128;             // centroids per tile (streamed)
constexpr int NCT = Kn / TN;         // 8 c tiles per CTA
constexpr int NT  = 256;             // threads per CTA

// f16 centroids + f16 squared norms (device global scratch).
__device__ __align__(16) uint32_t g_cb[(size_t)Gn * Kn * (RB / 4)];
__device__ __align__(16) unsigned short g_c2h[Gn * Kn];

// Dynamic smem (bytes). Slot = 16KB main (128B rows, XOR swizzle) + 256B norms.
// x resident in slot 0; c triple-buffered in slots 1..3.
constexpr int SLOT = 16640;          // 16384 + 256
constexpr int XS0  = 0;
constexpr int CBB  = SLOT;           // first c buffer
constexpr int SMEM_TOTAL = SLOT * 4; // 66560 B

__device__ __forceinline__ uint32_t smem_u32(const void* p) {
    uint32_t a;
    asm("{ .reg .u64 t; cvta.to.shared.u64 t, %1; cvt.u32.u64 %0, t; }"
        : "=r"(a) : "l"(p));
    return a;
}
__device__ __forceinline__ float fsqrt_approx(float v) {
    float r;
    asm("sqrt.approx.f32 %0, %1;" : "=f"(r) : "f"(v));
    return r;
}
__device__ __forceinline__ uint32_t pack_f16(float lo, float hi) {
    __half2 h = __floats2half2_rn(lo, hi);   // .x = lo (low half)
    uint32_t u;
    memcpy(&u, &h, 4);
    return u;
}
__device__ __forceinline__ uint32_t hadd2u(uint32_t a, uint32_t b) {
    uint32_t r;
    asm("add.rn.f16x2 %0, %1, %2;" : "=r"(r) : "r"(a), "r"(b));
    return r;
}
__device__ __forceinline__ void cp16(uint32_t dst, const void* src) {
    asm volatile("cp.async.cg.shared.global [%0], [%1], 16;"
                 :: "r"(dst), "l"(src) : "memory");
}
#define CP_COMMIT() asm volatile("cp.async.commit_group;" ::: "memory")
#define CP_WAIT0()  asm volatile("cp.async.wait_group 0;" ::: "memory")
#define CP_WAIT1()  asm volatile("cp.async.wait_group 1;" ::: "memory")

__device__ __forceinline__ void ldsm_x4(uint32_t r[4], uint32_t addr) {
    asm volatile("ldmatrix.sync.aligned.m8n8.x4.shared.b16 {%0,%1,%2,%3}, [%4];"
                 : "=r"(r[0]), "=r"(r[1]), "=r"(r[2]), "=r"(r[3]) : "r"(addr));
}
// f16 x f16 -> f16 accumulate: D/C in 2 regs (f16x2 each)
__device__ __forceinline__ void mma_f16(uint32_t c[2], const uint32_t a[4],
                                        uint32_t b0, uint32_t b1) {
    asm volatile(
        "mma.sync.aligned.m16n8k16.row.col.f16.f16.f16.f16 "
        "{%0,%1}, {%2,%3,%4,%5}, {%6,%7}, {%0,%1};"
        : "+r"(c[0]), "+r"(c[1])
        : "r"(a[0]), "r"(a[1]), "r"(a[2]), "r"(a[3]), "r"(b0), "r"(b1));
}
__device__ __forceinline__ void stg_cs2(float* p, float a, float b) {
    asm volatile("st.global.cs.v2.f32 [%0], {%1, %2};"
                 :: "l"(p), "f"(a), "f"(b) : "memory");
}
__device__ __forceinline__ void sts128(uint32_t a, uint4 v) {
    asm volatile("st.shared.v4.b32 [%0], {%1,%2,%3,%4};"
                 :: "r"(a), "r"(v.x), "r"(v.y), "r"(v.z), "r"(v.w) : "memory");
}

// ---------------------------------------------------------------------------
// Pass 1 (tiny): f16 centroid rows + f16 squared norms (fp32-exact reduce).
// ---------------------------------------------------------------------------
__global__ __launch_bounds__(256)
void prep_c_kernel(const float* __restrict__ cen)
{
    const int t = blockIdx.x * blockDim.x + threadIdx.x;
    if (t >= Gn * Kn) return;
    const float4* src = (const float4*)(cen + (size_t)t * Dn);
    uint4* dst = (uint4*)(g_cb + (size_t)t * (RB / 4));

    float s = 0.f;
#pragma unroll
    for (int i = 0; i < 8; i++) {
        float4 v0 = src[2 * i];
        float4 v1 = src[2 * i + 1];
        s = fmaf(v0.x, v0.x, s); s = fmaf(v0.y, v0.y, s);
        s = fmaf(v0.z, v0.z, s); s = fmaf(v0.w, v0.w, s);
        s = fmaf(v1.x, v1.x, s); s = fmaf(v1.y, v1.y, s);
        s = fmaf(v1.z, v1.z, s); s = fmaf(v1.w, v1.w, s);
        uint4 o;
        o.x = pack_f16(v0.x, v0.y); o.y = pack_f16(v0.z, v0.w);
        o.z = pack_f16(v1.x, v1.y); o.w = pack_f16(v1.z, v1.w);
        dst[i] = o;
    }
    __half h = __float2half_rn(s);
    unsigned short hb;
    memcpy(&hb, &h, 2);
    g_c2h[t] = hb;
}

// c tile loader: 1024 main 16B chunks + 16 norm chunks over 256 threads.
__device__ __forceinline__ void load_ctile(uint32_t base, const char* gsrc,
                                           const char* c2src, int tid)
{
#pragma unroll
    for (int i = 0; i < 5; i++) {
        const int idx = i * NT + tid;
        if (idx < 1024) {
            const int row = idx >> 3;
            const int q   = idx & 7;
            cp16(base + row * 128 + ((q ^ (row & 7)) << 4), gsrc + row * RB + q * 16);
        } else if (idx < 1040) {
            const int j = idx - 1024;
            cp16(base + 16384 + j * 16, c2src + j * 16);
        }
    }
}

// ---------------------------------------------------------------------------
// Pass 2: x resident (converted in-kernel), A-fragments hoisted, 8 c tiles
// streamed. acc init = f16(x2+c2). Epilogue BLOCKED BY NT-PAIR so stores
// interleave with MMA work (smooth DRAM write stream).
// ---------------------------------------------------------------------------
__global__ __launch_bounds__(NT, 2)
void dist_kernel(const float* __restrict__ x, float* __restrict__ out)
{
    extern __shared__ __align__(128) char smem[];
    const uint32_t sb = smem_u32(smem);

    const int tid  = threadIdx.x;
    const int wid  = tid >> 5;
    const int lane = tid & 31;
    const int qid  = lane >> 2;     // 0..7
    const int t4   = lane & 3;      // 0..3

    const int g  = blockIdx.y;
    const int b0 = blockIdx.x * TM;

    const char* cgb = (const char*)g_cb + (size_t)(g * Kn) * RB;
    const char* c2g = (const char*)g_c2h + (size_t)(g * Kn) * 2;

    // ---- Prologue: issue c tiles 0 and 1 (overlaps the x conversion). ----
    load_ctile(sb + CBB, cgb, c2g, tid);
    CP_COMMIT();
    load_ctile(sb + 2 * CBB, cgb + (size_t)TN * RB, c2g + TN * 2, tid);
    CP_COMMIT();

    // ---- Convert resident x tile: fp32 -> f16 (-2x), f16 norm to smem. ----
    {
        const int row  = tid >> 1;
        const int part = tid & 1;
        const float4* xr = (const float4*)(x + (size_t)(g * Bn + b0 + row) * Dn)
                           + part * 8;
        float4 v[8];
#pragma unroll
        for (int i = 0; i < 8; i++) v[i] = xr[i];

        float s = 0.f;
#pragma unroll
        for (int i = 0; i < 8; i++) {
            s = fmaf(v[i].x, v[i].x, s); s = fmaf(v[i].y, v[i].y, s);
            s = fmaf(v[i].z, v[i].z, s); s = fmaf(v[i].w, v[i].w, s);
        }
        s += __shfl_xor_sync(0xffffffffu, s, 1);   // full row norm in both lanes

#pragma unroll
        for (int j = 0; j < 4; j++) {
            uint4 m;
            m.x = pack_f16(-2.f * v[2*j].x,   -2.f * v[2*j].y);
            m.y = pack_f16(-2.f * v[2*j].z,   -2.f * v[2*j].w);
            m.z = pack_f16(-2.f * v[2*j+1].x, -2.f * v[2*j+1].y);
            m.w = pack_f16(-2.f * v[2*j+1].z, -2.f * v[2*j+1].w);
            const int q = part * 4 + j;
            sts128(sb + XS0 + row * 128 + ((q ^ (row & 7)) << 4), m);
        }

        if (part == 0) {
            __half h = __float2half_rn(s);
            unsigned short hb;
            memcpy(&hb, &h, 2);
            asm volatile("st.shared.u16 [%0], %1;"
                         :: "r"(sb + XS0 + 16384 + (uint32_t)(row * 2)), "h"(hb)
                         : "memory");
        }
    }
    __syncthreads();   // x tile + norms visible

    const int wm = (wid >> 2) * 64;   // warp m-base: 0 / 64
    const int wn = (wid & 3) * 32;    // warp n-base: 0/32/64/96

    // Per-lane ldmatrix geometry.
    const int swz    = lane & 7;
    const int a_row  = lane & 15;                        // + wm + mt*16
    const int a_qoff = lane >> 4;                        // 0/1
    const int b_nrow = ((lane >> 4) << 3) + (lane & 7);  // + wn (+16 per pair)
    const int b_qoff = (lane >> 3) & 1;                  // 0/1

    const uint32_t xs0 = sb + XS0;

    // ---- HOIST: main A fragments for all 4 k-steps x 4 m-tiles (64 regs).
    uint32_t afr[4][4][4];
#pragma unroll
    for (int ks = 0; ks < 4; ks++) {
        const uint32_t qa = (uint32_t)(((2 * ks + a_qoff) ^ swz) << 4);
#pragma unroll
        for (int mt = 0; mt < 4; mt++)
            ldsm_x4(afr[ks][mt], xs0 + (uint32_t)((wm + mt * 16 + a_row) * 128) + qa);
    }

    // ---- HOIST: x2 duplicated into half2 per (mt, h) row. ----
    uint32_t x2d[4][2];
#pragma unroll
    for (int mt = 0; mt < 4; mt++)
#pragma unroll
        for (int h = 0; h < 2; h++) {
            const int row = wm + mt * 16 + h * 8 + qid;
            unsigned short hb;
            asm volatile("ld.shared.u16 %0, [%1];"
                         : "=h"(hb) : "r"(xs0 + 16384 + (uint32_t)(row * 2)));
            x2d[mt][h] = (uint32_t)hb | ((uint32_t)hb << 16);
        }

    // Rotating c-buffer bases.
    uint32_t ccur = sb + CBB;
    uint32_t cnxt = sb + 2 * CBB;
    uint32_t cpf  = sb + 3 * CBB;

#pragma unroll 1
    for (int ct = 0; ct < NCT; ct++) {
        if (ct == NCT - 1) { CP_WAIT0(); } else { CP_WAIT1(); }
        __syncthreads();

        if (ct + 2 < NCT) {
            load_ctile(cpf, cgb + (size_t)(ct + 2) * TN * RB,
                       c2g + (ct + 2) * TN * 2, tid);
            CP_COMMIT();
        }

        const uint32_t cs0 = ccur;
        const int k0 = ct * TN;

        // ---- nt-pair blocks: compute 32 MMAs, then store, per pair. ----
#pragma unroll
        for (int ntp = 0; ntp < 2; ntp++) {
            const int nbase = wn + ntp * 16;   // B window [nbase, nbase+16)

            // B fragments for BOTH nts of this pair, all 4 k-steps (16 regs).
            uint32_t bf[4][2][2];              // [ks][ntloc][half]
#pragma unroll
            for (int ks = 0; ks < 4; ks++) {
                const uint32_t qb = (uint32_t)(((2 * ks + b_qoff) ^ swz) << 4);
                uint32_t r[4];
                ldsm_x4(r, cs0 + (uint32_t)((nbase + b_nrow) * 128) + qb);
                bf[ks][0][0] = r[0]; bf[ks][0][1] = r[1];
                bf[ks][1][0] = r[2]; bf[ks][1][1] = r[3];
            }

            // c2 pairs (broadcast LDS) + acc init = f16x2(x2 + c2).
            uint32_t acc[4][2][2];             // [mt][ntloc][half]
#pragma unroll
            for (int ntloc = 0; ntloc < 2; ntloc++) {
                uint32_t c2p;
                asm volatile("ld.shared.b32 %0, [%1];"
                             : "=r"(c2p)
                             : "r"(ccur + 16384 +
                                   (uint32_t)((nbase + ntloc * 8 + 2 * t4) * 2)));
#pragma unroll
                for (int mt = 0; mt < 4; mt++) {
                    acc[mt][ntloc][0] = hadd2u(x2d[mt][0], c2p);
                    acc[mt][ntloc][1] = hadd2u(x2d[mt][1], c2p);
                }
            }

            // MMAs: 4 ks x 4 mt x 2 ntloc.
#pragma unroll
            for (int ks = 0; ks < 4; ks++)
#pragma unroll
                for (int mt = 0; mt < 4; mt++)
#pragma unroll
                    for (int ntloc = 0; ntloc < 2; ntloc++)
                        mma_f16(acc[mt][ntloc], afr[ks][mt],
                                bf[ks][ntloc][0], bf[ks][ntloc][1]);

            // Store this pair's results now (interleaves with next pair's MMAs).
#pragma unroll
            for (int mt = 0; mt < 4; mt++) {
                const int row0 = b0 + wm + mt * 16 + qid;
                float* opa = out + (size_t)(g * Bn + row0) * Kn
                                 + k0 + nbase + 2 * t4;
                float* opb = opa + (size_t)8 * Kn;
#pragma unroll
                for (int ntloc = 0; ntloc < 2; ntloc++) {
                    __half2 h0, h1;
                    memcpy(&h0, &acc[mt][ntloc][0], 4);
                    memcpy(&h1, &acc[mt][ntloc][1], 4);
                    float2 f0 = __half22float2(h0);
                    float2 f1 = __half22float2(h1);
                    stg_cs2(opa + ntloc * 8, fsqrt_approx(f0.x), fsqrt_approx(f0.y));
                    stg_cs2(opb + ntloc * 8, fsqrt_approx(f1.x), fsqrt_approx(f1.y));
                }
            }
        }

        // Rotate c buffers.
        const uint32_t t = ccur;
        ccur = cnxt; cnxt = cpf; cpf = t;
    }
}

extern "C" void kernel_launch(void* const* d_in, const int* in_sizes, int n_in,
                              void* d_out, int out_size)
{
    const float* x   = (const float*)d_in[0];   // [G, B, D] fp32
    const float* cen = (const float*)d_in[1];   // [G, K, D] fp32
    float* out = (float*)d_out;                 // [G, B, K] fp32

    static bool attr_set = false;
    if (!attr_set) {
        cudaFuncSetAttribute(dist_kernel,
                             cudaFuncAttributeMaxDynamicSharedMemorySize, SMEM_TOTAL);
        attr_set = true;
    }

    prep_c_kernel<<<(Gn * Kn + 255) / 256, 256>>>(cen);

    dim3 grid(Bn / TM, Gn);                     // (64, 16) = 1024 CTAs
    dist_kernel<<<grid, NT, SMEM_TOTAL>>>(x, out);
}